// round 13
// baseline (speedup 1.0000x reference)
#include <cuda_runtime.h>
#include <math.h>

// Gaussian-mixture splat renderer, forward-differenced along grid columns.
// R12 math (packed k-pair chains + packed epilogue, XOR-swizzled SMEM-staged
// coalesced stores) with the work quantum halved: PIX=16 -> 3456 blocks vs
// 1776 resident -> ~2 waves with continuous backfill (kills the single-wave
// finish-spread idle tail that pinned achieved occupancy at ~50%).
//
// c = x_idx*H + y_idx ; px = x_idx/(W-1), py = y_idx/(H-1).
// Per Gaussian k (prescaled by SC = sqrt(0.5*log2 e)):
//   t0 = s10*py + (s00*px + C0),  t1 = s11*py + A1,  e_k = exp2(-(t0^2+t1^2))
// FD along a column: e <- e*r, r <- r*rr, rr = exp2(-2 h^2 (s10^2+s11^2))
// out = saturate( sum_k w_k e_k / max(1e-7, sum_k e_k) )

#define NK 4
#define PIX 16
#define THR 128          // 4 warps
#define WARPS 4
#define GM_EPS 1e-7f

typedef unsigned long long u64t;

__device__ __forceinline__ float ex2(float x) {
    float y; asm("ex2.approx.ftz.f32 %0, %1;" : "=f"(y) : "f"(x)); return y;
}
__device__ __forceinline__ u64t pk2(float lo, float hi) {
    u64t r; asm("mov.b64 %0, {%1, %2};" : "=l"(r) : "f"(lo), "f"(hi)); return r;
}
__device__ __forceinline__ void upk2(u64t v, float& lo, float& hi) {
    asm("mov.b64 {%0, %1}, %2;" : "=f"(lo), "=f"(hi) : "l"(v));
}
__device__ __forceinline__ u64t mul2(u64t a, u64t b) {
    u64t d; asm("mul.rn.f32x2 %0, %1, %2;" : "=l"(d) : "l"(a), "l"(b)); return d;
}
__device__ __forceinline__ u64t add2(u64t a, u64t b) {
    u64t d; asm("add.rn.f32x2 %0, %1, %2;" : "=l"(d) : "l"(a), "l"(b)); return d;
}
__device__ __forceinline__ u64t fma2(u64t a, u64t b, u64t c) {
    u64t d; asm("fma.rn.f32x2 %0, %1, %2, %3;" : "=l"(d) : "l"(a), "l"(b), "l"(c)); return d;
}

// ---------------------------------------------------------------------------
// Main kernel. Lane l of global-warp gw owns pixels [gw*512 + 16l, +16).
// Requires H % 16 == 0 and HW % 2048 == 0.
//
// SMEM tile (per warp, 128 float4 = 2048 B, XOR-swizzled, no padding):
//   write:  tw[4*l + (g ^ ((l>>1) & 3))]       g = group 0..3
//   read :  output float4 f = 32*i + l: producer lane lp = 8i+(l>>2),
//           group l&3  ->  tw[4*lp + ((l&3) ^ ((lp>>1) & 3))]
// Both patterns hit 8 distinct slot-mod-8 values per 8-lane phase.
// ---------------------------------------------------------------------------
__global__ void __launch_bounds__(THR, 12) gmix_fd(
    const float* __restrict__ params,
    float* __restrict__ out,
    int H, int HW, float inv_wm1, float inv_hm1)
{
    __shared__ float4 tile[WARPS][128];   // 8192 B total

    const int warp = threadIdx.x >> 5;
    const int lane = threadIdx.x & 31;
    const int gw   = blockIdx.x * WARPS + warp;
    const int n    = blockIdx.y;
    const int c0   = gw * (32 * PIX) + lane * PIX;
    if (c0 >= HW) return;

    const float4* p4 = reinterpret_cast<const float4*>(params + n * 28);
    const float4 MUX = __ldg(p4 + 0);
    const float4 MUY = __ldg(p4 + 1);
    const float4 WKV = __ldg(p4 + 2);
    const float4 SG0 = __ldg(p4 + 3);   // {s00, s01(ignored), s10, s11}
    const float4 SG1 = __ldg(p4 + 4);
    const float4 SG2 = __ldg(p4 + 5);
    const float4 SG3 = __ldg(p4 + 6);

    const float mux[NK] = {MUX.x, MUX.y, MUX.z, MUX.w};
    const float muy[NK] = {MUY.x, MUY.y, MUY.z, MUY.w};
    const float SC = 0.84932180f;       // sqrt(0.5 * log2 e)
    const float s00[NK] = {SG0.x * SC, SG1.x * SC, SG2.x * SC, SG3.x * SC};
    const float s10[NK] = {SG0.z * SC, SG1.z * SC, SG2.z * SC, SG3.z * SC};
    const float s11[NK] = {SG0.w * SC, SG1.w * SC, SG2.w * SC, SG3.w * SC};

    const int   x_idx = c0 / H;
    const int   y0    = c0 - x_idx * H;
    const float px    = (float)x_idx * inv_wm1;
    const float py0   = (float)y0 * inv_hm1;
    const float h     = inv_hm1;

    // Derive FD constants, seed e and r at the first pixel of this run.
    float es[NK], rs[NK], rrs[NK];
#pragma unroll
    for (int k = 0; k < NK; k++) {
        const float C0  = -(s00[k] * mux[k] + s10[k] * muy[k]);
        const float A1  = -s11[k] * muy[k];
        const float a   = fmaf(s10[k], s10[k], s11[k] * s11[k]);
        const float w0n = -(h * h) * a;
        const float un  = -2.0f * h * s10[k];
        const float vn  = -2.0f * h * s11[k];
        rrs[k] = ex2(w0n + w0n);

        const float a0 = fmaf(s00[k], px, C0);
        const float t0 = fmaf(s10[k], py0, a0);
        const float t1 = fmaf(s11[k], py0, A1);
        es[k] = ex2(fmaf(-t0, t0, -t1 * t1));
        rs[k] = ex2(fmaf(un, t0, fmaf(vn, t1, w0n)));
    }

    // Packed chain state over k-pairs.
    u64t E01 = pk2(es[0], es[1]), E23 = pk2(es[2], es[3]);
    u64t R01 = pk2(rs[0], rs[1]), R23 = pk2(rs[2], rs[3]);
    const u64t RR01 = pk2(rrs[0], rrs[1]), RR23 = pk2(rrs[2], rrs[3]);
    const u64t W01  = pk2(WKV.x, WKV.y),   W23  = pk2(WKV.z, WKV.w);

    float4* tw = tile[warp];
    const int wbase = 4 * lane;
    const int wxor  = (lane >> 1) & 3;

#pragma unroll
    for (int grp = 0; grp < PIX / 4; grp++) {
        float4 res;
        float* rp = &res.x;
#pragma unroll
        for (int q = 0; q < 4; q++) {
            if (!(grp == 0 && q == 0)) {
                E01 = mul2(E01, R01);
                E23 = mul2(E23, R23);
                R01 = mul2(R01, RR01);
                R23 = mul2(R23, RR23);
            }
            const u64t G2 = add2(E01, E23);
            const u64t A2 = fma2(W01, E01, mul2(W23, E23));
            float g0, g1, a0, a1;
            upk2(G2, g0, g1);
            upk2(A2, a0, a1);
            rp[q] = __saturatef(
                __fdividef(a0 + a1, fmaxf(GM_EPS, g0 + g1)));
        }
        tw[wbase + (grp ^ wxor)] = res;            // STS.128, conflict-free
    }

    __syncwarp();

    // Coalesced drain: warp writes 4 x 512B contiguous chunks.
    float4* ob = reinterpret_cast<float4*>(out + (size_t)n * (size_t)HW
                                               + (size_t)gw * (32 * PIX));
#pragma unroll
    for (int i = 0; i < PIX / 4; i++) {
        const int lp = 8 * i + (lane >> 2);
        ob[32 * i + lane] = tw[4 * lp + ((lane & 3) ^ ((lp >> 1) & 3))];
    }
}

// ---------------------------------------------------------------------------
// Fallback: per-pixel direct evaluation (odd shapes).
// ---------------------------------------------------------------------------
__global__ void __launch_bounds__(256) gmix_generic(
    const float* __restrict__ params,
    float* __restrict__ out,
    int H, int HW, float inv_wm1, float inv_hm1)
{
    const int n = blockIdx.y;
    const float* p = params + n * 28;
    float mux[NK], muy[NK], wkk[NK], s00[NK], s10[NK], s11[NK];
#pragma unroll
    for (int k = 0; k < NK; k++) {
        mux[k] = __ldg(p + k);        muy[k] = __ldg(p + 4 + k);
        wkk[k] = __ldg(p + 8 + k);
        s00[k] = __ldg(p + 12 + 4*k + 0);
        s10[k] = __ldg(p + 12 + 4*k + 2);
        s11[k] = __ldg(p + 12 + 4*k + 3);
    }
    const int c = blockIdx.x * blockDim.x + threadIdx.x;
    if (c >= HW) return;
    const int x_idx = c / H, y_idx = c - x_idx * H;
    const float px = (float)x_idx * inv_wm1, py = (float)y_idx * inv_hm1;
    float g = 0.0f, acc = 0.0f;
#pragma unroll
    for (int k = 0; k < NK; k++) {
        const float d0 = px - mux[k], d1 = py - muy[k];
        const float t0 = fmaf(s00[k], d0, s10[k] * d1);
        const float t1 = s11[k] * d1;
        const float e  = __expf(-0.5f * fmaf(t0, t0, t1 * t1));
        g += e;
        acc = fmaf(wkk[k], e, acc);
    }
    out[(size_t)n * (size_t)HW + c] =
        __saturatef(__fdividef(acc, fmaxf(GM_EPS, g)));
}

// ---------------------------------------------------------------------------
extern "C" void kernel_launch(void* const* d_in, const int* in_sizes, int n_in,
                              void* d_out, int out_size)
{
    int pi = 0;
    for (int i = 1; i < n_in; i++)
        if (in_sizes[i] > in_sizes[pi]) pi = i;
    const float* params = (const float*)d_in[pi];

    const int N  = in_sizes[pi] / 28;
    const int HW = out_size / N;
    int H = (int)(sqrt((double)HW) + 0.5);
    while (H > 1 && (HW % H) != 0) H--;
    const int W = HW / H;

    const float inv_wm1 = 1.0f / (float)(W - 1);
    const float inv_hm1 = 1.0f / (float)(H - 1);

    const int px_per_block = THR * PIX;   // 2048
    if ((H % PIX) == 0 && (HW % px_per_block) == 0) {
        dim3 grid(HW / px_per_block, N);
        gmix_fd<<<grid, THR>>>(params, (float*)d_out,
                               H, HW, inv_wm1, inv_hm1);
    } else {
        const int threads = 256;
        dim3 grid((HW + threads - 1) / threads, N);
        gmix_generic<<<grid, threads>>>(params, (float*)d_out,
                                        H, HW, inv_wm1, inv_hm1);
    }
}

// round 14
// speedup vs baseline: 1.0521x; 1.0521x over previous
#include <cuda_runtime.h>
#include <math.h>

// Gaussian-mixture splat renderer, forward-differenced along grid columns.
// R13 kernel (PIX=16 two-wave backfill, packed k-pair chains, XOR-swizzled
// SMEM-staged coalesced stores) with __launch_bounds__(128,16): forces 32
// regs/thread so 16 CTAs/SM (64 warps = 100% theoretical occ) are resident.
//
// c = x_idx*H + y_idx ; px = x_idx/(W-1), py = y_idx/(H-1).
// Per Gaussian k (prescaled by SC = sqrt(0.5*log2 e)):
//   t0 = s10*py + (s00*px + C0),  t1 = s11*py + A1,  e_k = exp2(-(t0^2+t1^2))
// FD along a column: e <- e*r, r <- r*rr, rr = exp2(-2 h^2 (s10^2+s11^2))
// out = saturate( sum_k w_k e_k / max(1e-7, sum_k e_k) )

#define NK 4
#define PIX 16
#define THR 128          // 4 warps
#define WARPS 4
#define GM_EPS 1e-7f

typedef unsigned long long u64t;

__device__ __forceinline__ float ex2(float x) {
    float y; asm("ex2.approx.ftz.f32 %0, %1;" : "=f"(y) : "f"(x)); return y;
}
__device__ __forceinline__ u64t pk2(float lo, float hi) {
    u64t r; asm("mov.b64 %0, {%1, %2};" : "=l"(r) : "f"(lo), "f"(hi)); return r;
}
__device__ __forceinline__ void upk2(u64t v, float& lo, float& hi) {
    asm("mov.b64 {%0, %1}, %2;" : "=f"(lo), "=f"(hi) : "l"(v));
}
__device__ __forceinline__ u64t mul2(u64t a, u64t b) {
    u64t d; asm("mul.rn.f32x2 %0, %1, %2;" : "=l"(d) : "l"(a), "l"(b)); return d;
}
__device__ __forceinline__ u64t add2(u64t a, u64t b) {
    u64t d; asm("add.rn.f32x2 %0, %1, %2;" : "=l"(d) : "l"(a), "l"(b)); return d;
}
__device__ __forceinline__ u64t fma2(u64t a, u64t b, u64t c) {
    u64t d; asm("fma.rn.f32x2 %0, %1, %2, %3;" : "=l"(d) : "l"(a), "l"(b), "l"(c)); return d;
}

// ---------------------------------------------------------------------------
// Main kernel. Lane l of global-warp gw owns pixels [gw*512 + 16l, +16).
// Requires H % 16 == 0 and HW % 2048 == 0.
//
// SMEM tile (per warp, 128 float4 = 2048 B, XOR-swizzled, no padding):
//   write:  tw[4*l + (g ^ ((l>>1) & 3))]       g = group 0..3
//   read :  output float4 f = 32*i + l: producer lane lp = 8i+(l>>2),
//           group l&3  ->  tw[4*lp + ((l&3) ^ ((lp>>1) & 3))]
// Both patterns hit 8 distinct slot-mod-8 values per 8-lane phase.
// ---------------------------------------------------------------------------
__global__ void __launch_bounds__(THR, 16) gmix_fd(
    const float* __restrict__ params,
    float* __restrict__ out,
    int H, int HW, float inv_wm1, float inv_hm1)
{
    __shared__ float4 tile[WARPS][128];   // 8192 B total

    const int warp = threadIdx.x >> 5;
    const int lane = threadIdx.x & 31;
    const int gw   = blockIdx.x * WARPS + warp;
    const int n    = blockIdx.y;
    const int c0   = gw * (32 * PIX) + lane * PIX;
    if (c0 >= HW) return;

    const float4* p4 = reinterpret_cast<const float4*>(params + n * 28);
    const float4 MUX = __ldg(p4 + 0);
    const float4 MUY = __ldg(p4 + 1);
    const float4 WKV = __ldg(p4 + 2);
    const float4 SG0 = __ldg(p4 + 3);   // {s00, s01(ignored), s10, s11}
    const float4 SG1 = __ldg(p4 + 4);
    const float4 SG2 = __ldg(p4 + 5);
    const float4 SG3 = __ldg(p4 + 6);

    const float mux[NK] = {MUX.x, MUX.y, MUX.z, MUX.w};
    const float muy[NK] = {MUY.x, MUY.y, MUY.z, MUY.w};
    const float SC = 0.84932180f;       // sqrt(0.5 * log2 e)
    const float s00[NK] = {SG0.x * SC, SG1.x * SC, SG2.x * SC, SG3.x * SC};
    const float s10[NK] = {SG0.z * SC, SG1.z * SC, SG2.z * SC, SG3.z * SC};
    const float s11[NK] = {SG0.w * SC, SG1.w * SC, SG2.w * SC, SG3.w * SC};

    const int   x_idx = c0 / H;
    const int   y0    = c0 - x_idx * H;
    const float px    = (float)x_idx * inv_wm1;
    const float py0   = (float)y0 * inv_hm1;
    const float h     = inv_hm1;

    // Derive FD constants, seed e and r at the first pixel of this run.
    float es[NK], rs[NK], rrs[NK];
#pragma unroll
    for (int k = 0; k < NK; k++) {
        const float C0  = -(s00[k] * mux[k] + s10[k] * muy[k]);
        const float A1  = -s11[k] * muy[k];
        const float a   = fmaf(s10[k], s10[k], s11[k] * s11[k]);
        const float w0n = -(h * h) * a;
        const float un  = -2.0f * h * s10[k];
        const float vn  = -2.0f * h * s11[k];
        rrs[k] = ex2(w0n + w0n);

        const float a0 = fmaf(s00[k], px, C0);
        const float t0 = fmaf(s10[k], py0, a0);
        const float t1 = fmaf(s11[k], py0, A1);
        es[k] = ex2(fmaf(-t0, t0, -t1 * t1));
        rs[k] = ex2(fmaf(un, t0, fmaf(vn, t1, w0n)));
    }

    // Packed chain state over k-pairs.
    u64t E01 = pk2(es[0], es[1]), E23 = pk2(es[2], es[3]);
    u64t R01 = pk2(rs[0], rs[1]), R23 = pk2(rs[2], rs[3]);
    const u64t RR01 = pk2(rrs[0], rrs[1]), RR23 = pk2(rrs[2], rrs[3]);
    const u64t W01  = pk2(WKV.x, WKV.y),   W23  = pk2(WKV.z, WKV.w);

    float4* tw = tile[warp];
    const int wbase = 4 * lane;
    const int wxor  = (lane >> 1) & 3;

#pragma unroll
    for (int grp = 0; grp < PIX / 4; grp++) {
        float4 res;
        float* rp = &res.x;
#pragma unroll
        for (int q = 0; q < 4; q++) {
            if (!(grp == 0 && q == 0)) {
                E01 = mul2(E01, R01);
                E23 = mul2(E23, R23);
                R01 = mul2(R01, RR01);
                R23 = mul2(R23, RR23);
            }
            const u64t G2 = add2(E01, E23);
            const u64t A2 = fma2(W01, E01, mul2(W23, E23));
            float g0, g1, a0, a1;
            upk2(G2, g0, g1);
            upk2(A2, a0, a1);
            rp[q] = __saturatef(
                __fdividef(a0 + a1, fmaxf(GM_EPS, g0 + g1)));
        }
        tw[wbase + (grp ^ wxor)] = res;            // STS.128, conflict-free
    }

    __syncwarp();

    // Coalesced drain: warp writes 4 x 512B contiguous chunks.
    float4* ob = reinterpret_cast<float4*>(out + (size_t)n * (size_t)HW
                                               + (size_t)gw * (32 * PIX));
#pragma unroll
    for (int i = 0; i < PIX / 4; i++) {
        const int lp = 8 * i + (lane >> 2);
        ob[32 * i + lane] = tw[4 * lp + ((lane & 3) ^ ((lp >> 1) & 3))];
    }
}

// ---------------------------------------------------------------------------
// Fallback: per-pixel direct evaluation (odd shapes).
// ---------------------------------------------------------------------------
__global__ void __launch_bounds__(256) gmix_generic(
    const float* __restrict__ params,
    float* __restrict__ out,
    int H, int HW, float inv_wm1, float inv_hm1)
{
    const int n = blockIdx.y;
    const float* p = params + n * 28;
    float mux[NK], muy[NK], wkk[NK], s00[NK], s10[NK], s11[NK];
#pragma unroll
    for (int k = 0; k < NK; k++) {
        mux[k] = __ldg(p + k);        muy[k] = __ldg(p + 4 + k);
        wkk[k] = __ldg(p + 8 + k);
        s00[k] = __ldg(p + 12 + 4*k + 0);
        s10[k] = __ldg(p + 12 + 4*k + 2);
        s11[k] = __ldg(p + 12 + 4*k + 3);
    }
    const int c = blockIdx.x * blockDim.x + threadIdx.x;
    if (c >= HW) return;
    const int x_idx = c / H, y_idx = c - x_idx * H;
    const float px = (float)x_idx * inv_wm1, py = (float)y_idx * inv_hm1;
    float g = 0.0f, acc = 0.0f;
#pragma unroll
    for (int k = 0; k < NK; k++) {
        const float d0 = px - mux[k], d1 = py - muy[k];
        const float t0 = fmaf(s00[k], d0, s10[k] * d1);
        const float t1 = s11[k] * d1;
        const float e  = __expf(-0.5f * fmaf(t0, t0, t1 * t1));
        g += e;
        acc = fmaf(wkk[k], e, acc);
    }
    out[(size_t)n * (size_t)HW + c] =
        __saturatef(__fdividef(acc, fmaxf(GM_EPS, g)));
}

// ---------------------------------------------------------------------------
extern "C" void kernel_launch(void* const* d_in, const int* in_sizes, int n_in,
                              void* d_out, int out_size)
{
    int pi = 0;
    for (int i = 1; i < n_in; i++)
        if (in_sizes[i] > in_sizes[pi]) pi = i;
    const float* params = (const float*)d_in[pi];

    const int N  = in_sizes[pi] / 28;
    const int HW = out_size / N;
    int H = (int)(sqrt((double)HW) + 0.5);
    while (H > 1 && (HW % H) != 0) H--;
    const int W = HW / H;

    const float inv_wm1 = 1.0f / (float)(W - 1);
    const float inv_hm1 = 1.0f / (float)(H - 1);

    const int px_per_block = THR * PIX;   // 2048
    if ((H % PIX) == 0 && (HW % px_per_block) == 0) {
        dim3 grid(HW / px_per_block, N);
        gmix_fd<<<grid, THR>>>(params, (float*)d_out,
                               H, HW, inv_wm1, inv_hm1);
    } else {
        const int threads = 256;
        dim3 grid((HW + threads - 1) / threads, N);
        gmix_generic<<<grid, threads>>>(params, (float*)d_out,
                                        H, HW, inv_wm1, inv_hm1);
    }
}